// round 15
// baseline (speedup 1.0000x reference)
#include <cuda_runtime.h>
#include <math.h>

// Problem constants (fixed by setup_inputs)
#define B_   64
#define S_   256
#define H_   768
#define D_   64
#define NEG_ 4
#define GRID_ 96   // (2*B + B*NEG) / 4 rows per block

#define EPSF 1e-15f
#define BNDF (1.0f - 1e-7f)

// Scratch (device globals — no allocation allowed)
__device__ float g_u   [B_ * D_];
__device__ float g_v   [B_ * D_];
__device__ float g_un  [B_ * NEG_ * D_];
__device__ float g_loss[B_];
__device__ int   g_bar1;   // zero-initialized; reset by last block each call
__device__ int   g_done;

// ---------------------------------------------------------------------------
// Fused kernel: stage1 (4 rows/block, 96 blocks) -> grid barrier ->
// stage2 (1 row per warp, warps 0..63 globally) -> done-counter ->
// last block reduces 64 losses and writes out[0], then resets counters.
// 96 blocks < 148 SMs => single wave, spin barrier is deadlock-free.
// ---------------------------------------------------------------------------
__global__ void __launch_bounds__(256, 1)
fused_kernel(const float* __restrict__ enc,
             const float* __restrict__ nenc,
             const float* __restrict__ m1,
             const float* __restrict__ m2,
             const float* __restrict__ mneg,
             const float* __restrict__ Wm,
             float* __restrict__ out)
{
    const int base = blockIdx.x * 4;
    const int tid  = threadIdx.x;
    const int warp = tid >> 5;
    const int lane = tid & 31;

    __shared__ float s_p[4][H_];      // expmap0(x) per row
    __shared__ float s_mx[4][D_];     // W @ p per row
    __shared__ int   s_sel[4];
    __shared__ float s_red[4][8];
    __shared__ float s_scale[4][2];   // [r][0]=scale, [r][1]=xn

    // ======================= STAGE 1 =======================
    const float* mask[4];
    const float* src[4];
    float*       dst[4];
    #pragma unroll
    for (int r = 0; r < 4; r++) {
        const int row = base + r;
        if (row < B_) {
            mask[r] = m1   + (size_t)row * S_;
            src[r]  = enc  + (size_t)row * S_ * H_;
            dst[r]  = g_u  + row * D_;
        } else if (row < 2 * B_) {
            const int q = row - B_;
            mask[r] = m2   + (size_t)q * S_;
            src[r]  = enc  + (size_t)q * S_ * H_;
            dst[r]  = g_v  + q * D_;
        } else {
            const int q = row - 2 * B_;
            mask[r] = mneg + (size_t)q * S_;
            src[r]  = nenc + (size_t)q * S_ * H_;
            dst[r]  = g_un + q * D_;
        }
    }

    // --- find one-hot indices ---
    #pragma unroll
    for (int r = 0; r < 4; r++)
        if (mask[r][tid] > 0.5f) s_sel[r] = tid;
    __syncthreads();

    // --- load selected rows + squared norms ---
    float acc[4] = {0.f, 0.f, 0.f, 0.f};
    #pragma unroll
    for (int r = 0; r < 4; r++) {
        const float* x = src[r] + (size_t)s_sel[r] * H_;
        #pragma unroll
        for (int i = 0; i < H_ / 256; i++) {
            float v = x[tid + i * 256];
            s_p[r][tid + i * 256] = v;
            acc[r] += v * v;
        }
    }
    #pragma unroll
    for (int o = 16; o; o >>= 1) {
        #pragma unroll
        for (int r = 0; r < 4; r++)
            acc[r] += __shfl_xor_sync(0xFFFFFFFFu, acc[r], o);
    }
    if (lane == 0) {
        #pragma unroll
        for (int r = 0; r < 4; r++) s_red[r][warp] = acc[r];
    }
    __syncthreads();
    if (tid < 4) {
        float n2 = 0.f;
        #pragma unroll
        for (int w = 0; w < 8; w++) n2 += s_red[tid][w];
        float n  = sqrtf(n2);
        float nc = fmaxf(n, EPSF);
        float t  = tanhf(nc);
        s_scale[tid][0] = t / nc;   // expmap0 scale
        s_scale[tid][1] = t;        // xn = ||p||
    }
    __syncthreads();

    // --- p = expmap0(x) ---
    {
        float es0 = s_scale[0][0], es1 = s_scale[1][0];
        float es2 = s_scale[2][0], es3 = s_scale[3][0];
        #pragma unroll
        for (int i = 0; i < H_ / 256; i++) {
            const int k = tid + i * 256;
            s_p[0][k] *= es0;  s_p[1][k] *= es1;
            s_p[2][k] *= es2;  s_p[3][k] *= es3;
        }
    }
    __syncthreads();

    // --- mx[r] = p[r] @ W^T : warp handles 8 W rows, W element reused x4 ---
    {
        float a[8][4];
        #pragma unroll
        for (int dd = 0; dd < 8; dd++)
            #pragma unroll
            for (int r = 0; r < 4; r++) a[dd][r] = 0.f;

        const float* wbase = Wm + (size_t)(warp * 8) * H_;
        #pragma unroll
        for (int i = 0; i < H_ / 32; i++) {
            const int k = lane + i * 32;
            const float p0 = s_p[0][k], p1 = s_p[1][k];
            const float p2 = s_p[2][k], p3 = s_p[3][k];
            #pragma unroll
            for (int dd = 0; dd < 8; dd++) {
                const float wv = __ldg(wbase + (size_t)dd * H_ + k);
                a[dd][0] = fmaf(p0, wv, a[dd][0]);
                a[dd][1] = fmaf(p1, wv, a[dd][1]);
                a[dd][2] = fmaf(p2, wv, a[dd][2]);
                a[dd][3] = fmaf(p3, wv, a[dd][3]);
            }
        }
        #pragma unroll
        for (int o = 16; o; o >>= 1)
            #pragma unroll
            for (int dd = 0; dd < 8; dd++)
                #pragma unroll
                for (int r = 0; r < 4; r++)
                    a[dd][r] += __shfl_xor_sync(0xFFFFFFFFu, a[dd][r], o);
        if (lane == 0) {
            #pragma unroll
            for (int dd = 0; dd < 8; dd++)
                #pragma unroll
                for (int r = 0; r < 4; r++)
                    s_mx[r][warp * 8 + dd] = a[dd][r];
        }
    }
    __syncthreads();

    // --- mobius_matvec scale per row: warp r handles row r ---
    if (warp < 4) {
        float a0 = s_mx[warp][lane];
        float a1 = s_mx[warp][lane + 32];
        float a  = a0 * a0 + a1 * a1;
        #pragma unroll
        for (int o = 16; o; o >>= 1) a += __shfl_xor_sync(0xFFFFFFFFu, a, o);
        if (lane == 0) {
            float mn  = sqrtf(a);
            float mnc = fmaxf(mn, EPSF);
            float xn  = fmaxf(s_scale[warp][1], EPSF);
            float at  = atanhf(fminf(xn, BNDF));
            s_scale[warp][0] = tanhf(mnc / xn * at) / mnc;
        }
    }
    __syncthreads();

    // --- write: 256 threads = 4 rows x 64 dims ---
    {
        const int r = tid >> 6;
        const int d = tid & 63;
        dst[r][d] = s_scale[r][0] * s_mx[r][d];
    }

    // ================== GRID BARRIER (single wave) ==================
    __threadfence();
    __syncthreads();
    if (tid == 0) {
        atomicAdd(&g_bar1, 1);
        while (atomicAdd(&g_bar1, 0) < GRID_) { }
    }
    __syncthreads();

    // ======================= STAGE 2 =======================
    // Global warp id; warps 0..63 (blocks 0..7) each handle one batch row.
    const int gw = blockIdx.x * 8 + warp;
    if (gw < B_) {
        const int b = gw;
        const float* u  = g_u  + b * D_;
        const float* v  = g_v  + b * D_;
        const float* un = g_un + (size_t)b * NEG_ * D_;

        const float u0 = u[lane],        u1 = u[lane + 32];
        const float v0 = v[lane],        v1 = v[lane + 32];
        const float w00 = un[lane],       w01 = un[lane + 32];
        const float w10 = un[64 + lane],  w11 = un[96 + lane];
        const float w20 = un[128 + lane], w21 = un[160 + lane];
        const float w30 = un[192 + lane], w31 = un[224 + lane];

        float x2 = u0 * u0 + u1 * u1;
        float y2 = v0 * v0 + v1 * v1;
        float xy = u0 * v0 + u1 * v1;
        float n0 = w00 * w00 + w01 * w01;
        float n1 = w10 * w10 + w11 * w11;
        float n2 = w20 * w20 + w21 * w21;
        float n3 = w30 * w30 + w31 * w31;
        float c0 = u0 * w00 + u1 * w01;
        float c1 = u0 * w10 + u1 * w11;
        float c2 = u0 * w20 + u1 * w21;
        float c3 = u0 * w30 + u1 * w31;

        #pragma unroll
        for (int o = 16; o; o >>= 1) {
            x2 += __shfl_xor_sync(0xFFFFFFFFu, x2, o);
            y2 += __shfl_xor_sync(0xFFFFFFFFu, y2, o);
            xy += __shfl_xor_sync(0xFFFFFFFFu, xy, o);
            n0 += __shfl_xor_sync(0xFFFFFFFFu, n0, o);
            n1 += __shfl_xor_sync(0xFFFFFFFFu, n1, o);
            n2 += __shfl_xor_sync(0xFFFFFFFFu, n2, o);
            n3 += __shfl_xor_sync(0xFFFFFFFFu, n3, o);
            c0 += __shfl_xor_sync(0xFFFFFFFFu, c0, o);
            c1 += __shfl_xor_sync(0xFFFFFFFFu, c1, o);
            c2 += __shfl_xor_sync(0xFFFFFFFFu, c2, o);
            c3 += __shfl_xor_sync(0xFFFFFFFFu, c3, o);
        }

        // Per-lane distance: lanes 0..3 -> negatives, lanes >=4 -> d(u,v).
        float A2, XY;
        if      (lane == 0) { A2 = n0; XY = c0; }
        else if (lane == 1) { A2 = n1; XY = c1; }
        else if (lane == 2) { A2 = n2; XY = c2; }
        else if (lane == 3) { A2 = n3; XY = c3; }
        else                { A2 = y2; XY = xy; }

        // ||mobius_add(-u, y)||^2 via dot-product algebra
        const float cA  = 1.0f - 2.0f * XY + A2;
        const float cB  = 1.0f - x2;
        const float den = fmaxf(1.0f - 2.0f * XY + x2 * A2, EPSF);
        float ms = cA * cA * x2 - 2.0f * cA * cB * XY + cB * cB * A2;
        ms = fmaxf(ms, 0.0f);
        const float dn = sqrtf(ms) / den;
        const float d  = 2.0f * atanhf(fminf(dn, BNDF));
        const float e  = expf(-d);

        const float Z1 = __shfl_sync(0xFFFFFFFFu, e, 0)
                       + __shfl_sync(0xFFFFFFFFu, e, 1)
                       + __shfl_sync(0xFFFFFFFFu, e, 2)
                       + __shfl_sync(0xFFFFFFFFu, e, 3);
        const float expneg = __shfl_sync(0xFFFFFFFFu, e, 4);

        // angle (computed on all lanes, overlaps the distance chain)
        const float euclid = sqrtf(fmaxf(x2 + y2 - 2.0f * xy, 0.0f));
        const float rad    = fmaxf(1.0f + x2 * y2 - 2.0f * xy, EPSF);
        const float aden   = fmaxf(sqrtf(y2) * euclid * sqrtf(rad), EPSF);
        float cosang = (xy * (1.0f + y2) - y2 * (1.0f + x2)) / aden;
        cosang = fminf(fmaxf(cosang, -BNDF), BNDF);
        const float ang = acosf(cosang);

        const float nsl = -logf(expneg / (Z1 + expneg));
        if (lane == 0) g_loss[b] = ang + nsl;  // 2(1-a)ang + 2a nsl, a=0.5
    }

    // ================== DONE + FINAL REDUCE ==================
    __threadfence();
    __syncthreads();
    if (tid == 0) {
        const int d = atomicAdd(&g_done, 1);
        if (d == GRID_ - 1) {
            // all 96 blocks fenced their work before incrementing
            float s = 0.f;
            #pragma unroll
            for (int i = 0; i < B_; i++) s += g_loss[i];
            out[0] = s * (1.0f / (float)B_);
            // reset counters for the next graph replay (everyone is past
            // both wait points; no thread reads these again this launch)
            atomicExch(&g_bar1, 0);
            atomicExch(&g_done, 0);
        }
    }
}

// ---------------------------------------------------------------------------
extern "C" void kernel_launch(void* const* d_in, const int* in_sizes, int n_in,
                              void* d_out, int out_size)
{
    const float* enc  = (const float*)d_in[0];  // [64,256,768]
    const float* nenc = (const float*)d_in[1];  // [256,256,768]
    const float* m1   = (const float*)d_in[2];  // [64,256,1]
    const float* m2   = (const float*)d_in[3];  // [64,256,1]
    const float* mneg = (const float*)d_in[4];  // [256,256,1]
    const float* Wm   = (const float*)d_in[5];  // [64,768]
    float* out = (float*)d_out;

    fused_kernel<<<GRID_, 256>>>(enc, nenc, m1, m2, mneg, Wm, out);
}

// round 16
// speedup vs baseline: 1.2590x; 1.2590x over previous
#include <cuda_runtime.h>
#include <math.h>

// Problem constants (fixed by setup_inputs)
#define B_   64
#define S_   256
#define H_   768
#define D_   64
#define NEG_ 4

#define EPSF 1e-15f
#define BNDF (1.0f - 1e-7f)

// Scratch (device globals — no allocation allowed)
__device__ float g_u [B_ * D_];
__device__ float g_v [B_ * D_];
__device__ float g_un[B_ * NEG_ * D_];

// ---------------------------------------------------------------------------
// Stage 1: 96 blocks x 4 rows (identical to the proven round-14 version).
// Row space [0,384): [0,64)->u, [64,128)->v, [128,384)->u_neg.
// ---------------------------------------------------------------------------
__global__ void __launch_bounds__(256, 4)
stage1_kernel(const float* __restrict__ enc,
              const float* __restrict__ nenc,
              const float* __restrict__ m1,
              const float* __restrict__ m2,
              const float* __restrict__ mneg,
              const float* __restrict__ Wm)
{
    const int base = blockIdx.x * 4;
    const int tid  = threadIdx.x;
    const int warp = tid >> 5;
    const int lane = tid & 31;

    __shared__ float s_p[4][H_];
    __shared__ float s_mx[4][D_];
    __shared__ int   s_sel[4];
    __shared__ float s_red[4][8];
    __shared__ float s_scale[4][2];

    const float* mask[4];
    const float* src[4];
    float*       dst[4];
    #pragma unroll
    for (int r = 0; r < 4; r++) {
        const int row = base + r;
        if (row < B_) {
            mask[r] = m1   + (size_t)row * S_;
            src[r]  = enc  + (size_t)row * S_ * H_;
            dst[r]  = g_u  + row * D_;
        } else if (row < 2 * B_) {
            const int q = row - B_;
            mask[r] = m2   + (size_t)q * S_;
            src[r]  = enc  + (size_t)q * S_ * H_;
            dst[r]  = g_v  + q * D_;
        } else {
            const int q = row - 2 * B_;
            mask[r] = mneg + (size_t)q * S_;
            src[r]  = nenc + (size_t)q * S_ * H_;
            dst[r]  = g_un + q * D_;
        }
    }

    #pragma unroll
    for (int r = 0; r < 4; r++)
        if (mask[r][tid] > 0.5f) s_sel[r] = tid;
    __syncthreads();

    float acc[4] = {0.f, 0.f, 0.f, 0.f};
    #pragma unroll
    for (int r = 0; r < 4; r++) {
        const float* x = src[r] + (size_t)s_sel[r] * H_;
        #pragma unroll
        for (int i = 0; i < H_ / 256; i++) {
            float v = x[tid + i * 256];
            s_p[r][tid + i * 256] = v;
            acc[r] += v * v;
        }
    }
    #pragma unroll
    for (int o = 16; o; o >>= 1) {
        #pragma unroll
        for (int r = 0; r < 4; r++)
            acc[r] += __shfl_xor_sync(0xFFFFFFFFu, acc[r], o);
    }
    if (lane == 0) {
        #pragma unroll
        for (int r = 0; r < 4; r++) s_red[r][warp] = acc[r];
    }
    __syncthreads();
    if (tid < 4) {
        float n2 = 0.f;
        #pragma unroll
        for (int w = 0; w < 8; w++) n2 += s_red[tid][w];
        float n  = sqrtf(n2);
        float nc = fmaxf(n, EPSF);
        float t  = tanhf(nc);
        s_scale[tid][0] = t / nc;
        s_scale[tid][1] = t;
    }
    __syncthreads();

    {
        float es0 = s_scale[0][0], es1 = s_scale[1][0];
        float es2 = s_scale[2][0], es3 = s_scale[3][0];
        #pragma unroll
        for (int i = 0; i < H_ / 256; i++) {
            const int k = tid + i * 256;
            s_p[0][k] *= es0;  s_p[1][k] *= es1;
            s_p[2][k] *= es2;  s_p[3][k] *= es3;
        }
    }
    __syncthreads();

    {
        float a[8][4];
        #pragma unroll
        for (int dd = 0; dd < 8; dd++)
            #pragma unroll
            for (int r = 0; r < 4; r++) a[dd][r] = 0.f;

        const float* wbase = Wm + (size_t)(warp * 8) * H_;
        #pragma unroll
        for (int i = 0; i < H_ / 32; i++) {
            const int k = lane + i * 32;
            const float p0 = s_p[0][k], p1 = s_p[1][k];
            const float p2 = s_p[2][k], p3 = s_p[3][k];
            #pragma unroll
            for (int dd = 0; dd < 8; dd++) {
                const float wv = __ldg(wbase + (size_t)dd * H_ + k);
                a[dd][0] = fmaf(p0, wv, a[dd][0]);
                a[dd][1] = fmaf(p1, wv, a[dd][1]);
                a[dd][2] = fmaf(p2, wv, a[dd][2]);
                a[dd][3] = fmaf(p3, wv, a[dd][3]);
            }
        }
        #pragma unroll
        for (int o = 16; o; o >>= 1)
            #pragma unroll
            for (int dd = 0; dd < 8; dd++)
                #pragma unroll
                for (int r = 0; r < 4; r++)
                    a[dd][r] += __shfl_xor_sync(0xFFFFFFFFu, a[dd][r], o);
        if (lane == 0) {
            #pragma unroll
            for (int dd = 0; dd < 8; dd++)
                #pragma unroll
                for (int r = 0; r < 4; r++)
                    s_mx[r][warp * 8 + dd] = a[dd][r];
        }
    }
    __syncthreads();

    if (warp < 4) {
        float a0 = s_mx[warp][lane];
        float a1 = s_mx[warp][lane + 32];
        float a  = a0 * a0 + a1 * a1;
        #pragma unroll
        for (int o = 16; o; o >>= 1) a += __shfl_xor_sync(0xFFFFFFFFu, a, o);
        if (lane == 0) {
            float mn  = sqrtf(a);
            float mnc = fmaxf(mn, EPSF);
            float xn  = fmaxf(s_scale[warp][1], EPSF);
            float at  = atanhf(fminf(xn, BNDF));
            s_scale[warp][0] = tanhf(mnc / xn * at) / mnc;
        }
    }
    __syncthreads();

    {
        const int r = tid >> 6;
        const int d = tid & 63;
        dst[r][d] = s_scale[r][0] * s_mx[r][d];
    }
}

// ---------------------------------------------------------------------------
// Stage 2: 1 block x 1024 threads = 64 groups of 16 lanes; ONE row per group,
// all 64 rows fully parallel (no serial row loop). Each lane holds 4 elements
// via float4 loads. Reductions use width=16 shuffles (4 levels).
// Lanes 0..3 of each group compute the 4 negative distances, lane 4 d(u,v) —
// all 5 transcendental chains run concurrently.
// ---------------------------------------------------------------------------
__device__ __forceinline__ float dot4(float4 a, float4 b) {
    return a.x * b.x + a.y * b.y + a.z * b.z + a.w * b.w;
}

__global__ void __launch_bounds__(1024, 1)
stage2_kernel(float* __restrict__ out)
{
    const int tid  = threadIdx.x;
    const int b    = tid >> 4;        // row 0..63
    const int l16  = tid & 15;        // lane within 16-group
    __shared__ float s_loss[B_];
    __shared__ float s_part[2];

    const float4* u4  = (const float4*)(g_u  + b * D_);
    const float4* v4  = (const float4*)(g_v  + b * D_);
    const float4* un4 = (const float4*)(g_un + (size_t)b * NEG_ * D_);

    const float4 uu = u4[l16];
    const float4 vv = v4[l16];
    const float4 w0 = un4[l16];
    const float4 w1 = un4[16 + l16];
    const float4 w2 = un4[32 + l16];
    const float4 w3 = un4[48 + l16];

    float x2 = dot4(uu, uu);
    float y2 = dot4(vv, vv);
    float xy = dot4(uu, vv);
    float n0 = dot4(w0, w0);
    float n1 = dot4(w1, w1);
    float n2 = dot4(w2, w2);
    float n3 = dot4(w3, w3);
    float c0 = dot4(uu, w0);
    float c1 = dot4(uu, w1);
    float c2 = dot4(uu, w2);
    float c3 = dot4(uu, w3);

    #pragma unroll
    for (int o = 8; o; o >>= 1) {
        x2 += __shfl_xor_sync(0xFFFFFFFFu, x2, o, 16);
        y2 += __shfl_xor_sync(0xFFFFFFFFu, y2, o, 16);
        xy += __shfl_xor_sync(0xFFFFFFFFu, xy, o, 16);
        n0 += __shfl_xor_sync(0xFFFFFFFFu, n0, o, 16);
        n1 += __shfl_xor_sync(0xFFFFFFFFu, n1, o, 16);
        n2 += __shfl_xor_sync(0xFFFFFFFFu, n2, o, 16);
        n3 += __shfl_xor_sync(0xFFFFFFFFu, n3, o, 16);
        c0 += __shfl_xor_sync(0xFFFFFFFFu, c0, o, 16);
        c1 += __shfl_xor_sync(0xFFFFFFFFu, c1, o, 16);
        c2 += __shfl_xor_sync(0xFFFFFFFFu, c2, o, 16);
        c3 += __shfl_xor_sync(0xFFFFFFFFu, c3, o, 16);
    }

    // Per-lane distance: lanes 0..3 -> negatives, lanes >=4 -> d(u,v).
    float A2, XY;
    if      (l16 == 0) { A2 = n0; XY = c0; }
    else if (l16 == 1) { A2 = n1; XY = c1; }
    else if (l16 == 2) { A2 = n2; XY = c2; }
    else if (l16 == 3) { A2 = n3; XY = c3; }
    else               { A2 = y2; XY = xy; }

    // ||mobius_add(-u, y)||^2 via dot-product algebra:
    //   cA = 1 - 2<u,y> + ||y||^2,  cB = 1 - ||u||^2
    //   ms = cA^2 x2 - 2 cA cB XY + cB^2 A2
    const float cA  = 1.0f - 2.0f * XY + A2;
    const float cB  = 1.0f - x2;
    const float den = fmaxf(1.0f - 2.0f * XY + x2 * A2, EPSF);
    float ms = cA * cA * x2 - 2.0f * cA * cB * XY + cB * cB * A2;
    ms = fmaxf(ms, 0.0f);
    const float dn = sqrtf(ms) / den;
    const float d  = 2.0f * atanhf(fminf(dn, BNDF));
    const float e  = expf(-d);

    const float Z1 = __shfl_sync(0xFFFFFFFFu, e, 0, 16)
                   + __shfl_sync(0xFFFFFFFFu, e, 1, 16)
                   + __shfl_sync(0xFFFFFFFFu, e, 2, 16)
                   + __shfl_sync(0xFFFFFFFFu, e, 3, 16);
    const float expneg = __shfl_sync(0xFFFFFFFFu, e, 4, 16);

    // angle (all lanes compute it; overlaps the distance chain)
    const float euclid = sqrtf(fmaxf(x2 + y2 - 2.0f * xy, 0.0f));
    const float rad    = fmaxf(1.0f + x2 * y2 - 2.0f * xy, EPSF);
    const float aden   = fmaxf(sqrtf(y2) * euclid * sqrtf(rad), EPSF);
    float cosang = (xy * (1.0f + y2) - y2 * (1.0f + x2)) / aden;
    cosang = fminf(fmaxf(cosang, -BNDF), BNDF);
    const float ang = acosf(cosang);

    const float nsl = -logf(expneg / (Z1 + expneg));
    if (l16 == 0) s_loss[b] = ang + nsl;   // 2(1-a)ang + 2a nsl, a = 0.5
    __syncthreads();

    if (tid < 64) {
        float l = s_loss[tid];
        #pragma unroll
        for (int o = 16; o; o >>= 1) l += __shfl_xor_sync(0xFFFFFFFFu, l, o);
        if ((tid & 31) == 0) s_part[tid >> 5] = l;
    }
    __syncthreads();
    if (tid == 0)
        out[0] = (s_part[0] + s_part[1]) * (1.0f / (float)B_);
}

// ---------------------------------------------------------------------------
extern "C" void kernel_launch(void* const* d_in, const int* in_sizes, int n_in,
                              void* d_out, int out_size)
{
    const float* enc  = (const float*)d_in[0];  // [64,256,768]
    const float* nenc = (const float*)d_in[1];  // [256,256,768]
    const float* m1   = (const float*)d_in[2];  // [64,256,1]
    const float* m2   = (const float*)d_in[3];  // [64,256,1]
    const float* mneg = (const float*)d_in[4];  // [256,256,1]
    const float* Wm   = (const float*)d_in[5];  // [64,768]
    float* out = (float*)d_out;

    stage1_kernel<<<(2 * B_ + B_ * NEG_) / 4, 256>>>(enc, nenc, m1, m2, mneg, Wm);
    stage2_kernel<<<1, 1024>>>(out);
}